// round 5
// baseline (speedup 1.0000x reference)
#include <cuda_runtime.h>
#include <float.h>

#define BB    8
#define NN    2048
#define KK    16
#define CIN   64
#define COUT  128
#define BN_EPS 1e-3f
#define LARGE_DIST 1e9f

#define SPLIT 8
#define CAND  (NN / SPLIT)   // 256
#define NPTS  (BB * NN)      // 16384

#define BKT 16

// ---- global scratch -------------------------------------------------------
__device__ float g_pd[NPTS * SPLIT * KK];
__device__ int   g_pi[NPTS * SPLIT * KK];
__device__ int   g_idx[NPTS * KK];
__device__ float g_h[(size_t)NPTS * 512];
__device__ float g_X[(size_t)NPTS * 256];
__device__ float g_lift[(size_t)NPTS * 16 * 64];
__device__ float g_tr[(size_t)NPTS * 1024];

// ---- packed fp32x2 helpers ------------------------------------------------
__device__ __forceinline__ unsigned long long pack2(float lo, float hi) {
    unsigned long long r;
    asm("mov.b64 %0, {%1, %2};" : "=l"(r) : "f"(lo), "f"(hi));
    return r;
}
__device__ __forceinline__ float2 unpack2(unsigned long long v) {
    float2 r;
    asm("mov.b64 {%0, %1}, %2;" : "=f"(r.x), "=f"(r.y) : "l"(v));
    return r;
}
__device__ __forceinline__ void ffma2(unsigned long long& a,
                                      unsigned long long x,
                                      unsigned long long y) {
    asm("fma.rn.f32x2 %0, %1, %2, %0;" : "+l"(a) : "l"(x), "l"(y));
}
__device__ __forceinline__ unsigned long long add2(unsigned long long x,
                                                   unsigned long long y) {
    unsigned long long r;
    asm("add.rn.f32x2 %0, %1, %2;" : "=l"(r) : "l"(x), "l"(y));
    return r;
}
__device__ __forceinline__ unsigned long long mul2(unsigned long long x,
                                                   unsigned long long y) {
    unsigned long long r;
    asm("mul.rn.f32x2 %0, %1, %2;" : "=l"(r) : "l"(x), "l"(y));
    return r;
}

// ---------------------------------------------------------------------------
// KNN
// ---------------------------------------------------------------------------
__device__ __forceinline__ void insert16(float* bd, int* bi, float d, int j) {
    bd[KK - 1] = d; bi[KK - 1] = j;
#pragma unroll
    for (int t = KK - 1; t > 0; --t) {
        if (bd[t] < bd[t - 1]) {
            float td = bd[t]; bd[t] = bd[t - 1]; bd[t - 1] = td;
            int   ti = bi[t]; bi[t] = bi[t - 1]; bi[t - 1] = ti;
        }
    }
}

__global__ __launch_bounds__(128)
void knn_part(const float* __restrict__ xyz,
              float* __restrict__ pd, int* __restrict__ pi) {
    __shared__ float s_nx[NN], s_ny[NN], s_nz[NN], s_pen[NN];
    const int tid = threadIdx.x;
    const int qg  = blockIdx.x >> 3;
    const int sp  = blockIdx.x & 7;
    const int g   = qg * 128 + tid;
    const int b   = g >> 11;
    const int n   = g & (NN - 1);

    for (int j = tid; j < NN; j += 128) {
        const float* p = xyz + ((size_t)b * NN + j) * 3;
        float x = p[0], y = p[1], z = p[2];
        bool v = (x != 0.0f || y != 0.0f || z != 0.0f);
        s_nx[j] = -x; s_ny[j] = -y; s_nz[j] = -z;
        s_pen[j] = v ? 0.0f : LARGE_DIST;
    }
    __syncthreads();

    const float* qp = xyz + ((size_t)b * NN + n) * 3;
    unsigned long long qx2 = pack2(qp[0], qp[0]);
    unsigned long long qy2 = pack2(qp[1], qp[1]);
    unsigned long long qz2 = pack2(qp[2], qp[2]);

    float bd[KK]; int bi[KK];
#pragma unroll
    for (int t = 0; t < KK; t++) { bd[t] = FLT_MAX; bi[t] = 0; }

    const unsigned long long* px2 = (const unsigned long long*)s_nx + sp * (CAND / 2);
    const unsigned long long* py2 = (const unsigned long long*)s_ny + sp * (CAND / 2);
    const unsigned long long* pz2 = (const unsigned long long*)s_nz + sp * (CAND / 2);
    const unsigned long long* pp2 = (const unsigned long long*)s_pen + sp * (CAND / 2);
    const int jbase = sp * CAND;

#pragma unroll 8
    for (int jj = 0; jj < CAND / 2; jj++) {
        unsigned long long dx2 = add2(qx2, px2[jj]);
        unsigned long long dy2 = add2(qy2, py2[jj]);
        unsigned long long dz2 = add2(qz2, pz2[jj]);
        unsigned long long d2  = mul2(dx2, dx2);
        ffma2(d2, dy2, dy2);
        ffma2(d2, dz2, dz2);
        d2 = add2(d2, pp2[jj]);
        float2 d = unpack2(d2);
        if (fminf(d.x, d.y) < bd[KK - 1]) {
            if (d.x < bd[KK - 1]) insert16(bd, bi, d.x, jbase + 2 * jj);
            if (d.y < bd[KK - 1]) insert16(bd, bi, d.y, jbase + 2 * jj + 1);
        }
    }

    float* po = pd + ((size_t)g * SPLIT + sp) * KK;
    int*   io = pi + ((size_t)g * SPLIT + sp) * KK;
#pragma unroll
    for (int t = 0; t < KK; t++) { po[t] = bd[t]; io[t] = bi[t]; }
}

__global__ __launch_bounds__(128)
void knn_merge(const float* __restrict__ pd, const int* __restrict__ pi,
               int* __restrict__ idx_out) {
    const int g = blockIdx.x * 128 + threadIdx.x;
    float bd[KK]; int bi[KK];
#pragma unroll
    for (int t = 0; t < KK; t++) { bd[t] = FLT_MAX; bi[t] = 0; }
    const float* pp = pd + (size_t)g * SPLIT * KK;
    const int*   ii = pi + (size_t)g * SPLIT * KK;
    for (int c = 0; c < SPLIT * KK; c++) {
        float d = pp[c];
        if (d < bd[KK - 1]) insert16(bd, bi, d, ii[c]);
    }
#pragma unroll
    for (int t = 0; t < KK; t++) idx_out[(size_t)g * KK + t] = bi[t];
}

// ---------------------------------------------------------------------------
// k2: h precompute
// ---------------------------------------------------------------------------
__global__ __launch_bounds__(256)
void h_kernel(const float* __restrict__ xyz, const int* __restrict__ idx,
              const float* __restrict__ w1, const float* __restrict__ b1,
              const float* __restrict__ gamma1, const float* __restrict__ beta1,
              const float* __restrict__ mean1, const float* __restrict__ var1,
              float* __restrict__ H) {
    __shared__ float sw[96], sb[32], ssc[32], ssh[32];
    const int tid = threadIdx.x;
    if (tid < 96) sw[tid] = w1[tid];
    if (tid < 32) {
        sb[tid] = b1[tid];
        float sc = gamma1[tid] * rsqrtf(var1[tid] + BN_EPS);
        ssc[tid] = sc;
        ssh[tid] = beta1[tid] - mean1[tid] * sc;
    }
    __syncthreads();

    const int g0 = blockIdx.x * 16;
    const int p  = tid >> 4;
    const int k  = tid & 15;
    const int g  = g0 + p;
    const int b  = g >> 11;
    const int n  = g & (NN - 1);
    const int nbr = idx[(size_t)g * KK + k];

    const float* qp = xyz + ((size_t)b * NN + n) * 3;
    const float* np = xyz + ((size_t)b * NN + nbr) * 3;
    float qx = qp[0], qy = qp[1], qz = qp[2];
    float px = np[0], py = np[1], pz = np[2];
    float nm = (px != 0.0f || py != 0.0f || pz != 0.0f) ? 1.0f : 0.0f;
    float r0 = nm * (px - qx), r1 = nm * (py - qy), r2 = nm * (pz - qz);

    float* dst = H + (size_t)g * 512 + k * 32;
#pragma unroll
    for (int d4 = 0; d4 < 32; d4 += 4) {
        float4 o;
        float* ov = (float*)&o;
#pragma unroll
        for (int q = 0; q < 4; q++) {
            int d = d4 + q;
            float v = r0 * sw[d] + r1 * sw[32 + d] + r2 * sw[64 + d] + sb[d];
            v = fmaxf(v, 0.0f);
            ov[q] = v * ssc[d] + ssh[d];
        }
        *(float4*)(dst + d4) = o;
    }
}

// ---------------------------------------------------------------------------
// SGEMM, 128x128 tile, 128 threads, 16x8 micro-tile (ratio 10.7 FFMA2:LDS).
// EPI 0: C = acc + bias[n]   EPI 1: C = relu(acc*sc+sh)*qmask
// ---------------------------------------------------------------------------
template<int NMAT, int KMAT, int EPI>
__global__ __launch_bounds__(128)
void sgemm3(const float* __restrict__ A, const float* __restrict__ B,
            const float* __restrict__ e0, const float* __restrict__ e1,
            const float* __restrict__ e2, const float* __restrict__ e3,
            const float* __restrict__ xyz, float* __restrict__ C) {
    __shared__ float As[BKT][128];
    __shared__ float Bs[BKT][128];
    __shared__ float smask[128];
    __shared__ float ssc[128], ssh[128];

    const int tid  = threadIdx.x;
    const int row0 = blockIdx.x * 128;
    const int col0 = blockIdx.y * 128;
    const int tx   = tid & 15;     // 8-col group
    const int ty   = tid >> 4;     // 16-row group (0..7)
    const int brr  = tid >> 5;     // B load row (0..3)
    const int bcc  = (tid & 31) * 4;

    if (EPI == 1) {
        const float* p = xyz + (size_t)(row0 + tid) * 3;
        smask[tid] = (p[0] != 0.0f || p[1] != 0.0f || p[2] != 0.0f) ? 1.0f : 0.0f;
        if (tid < NMAT) {
            float sc = e0[tid] * rsqrtf(e3[tid] + BN_EPS);
            ssc[tid] = sc;
            ssh[tid] = e1[tid] - e2[tid] * sc;
        }
    }

    unsigned long long acc[16][4];
#pragma unroll
    for (int i = 0; i < 16; i++)
#pragma unroll
        for (int q = 0; q < 4; q++) acc[i][q] = 0ull;

    const float* arow = A + (size_t)(row0 + tid) * KMAT;

    for (int k0 = 0; k0 < KMAT; k0 += BKT) {
        __syncthreads();
        // A tile: thread tid loads row tid, 16 k-values -> As[k][row]
#pragma unroll
        for (int h = 0; h < 4; h++) {
            float4 a = *(const float4*)(arow + k0 + h * 4);
            As[h * 4 + 0][tid] = a.x;
            As[h * 4 + 1][tid] = a.y;
            As[h * 4 + 2][tid] = a.z;
            As[h * 4 + 3][tid] = a.w;
        }
        // B tile 16x128
#pragma unroll
        for (int h = 0; h < 4; h++) {
            *(float4*)&Bs[brr + h * 4][bcc] =
                *(const float4*)(B + (size_t)(k0 + brr + h * 4) * NMAT + col0 + bcc);
        }
        __syncthreads();

#pragma unroll
        for (int kk = 0; kk < BKT; kk++) {
            float a[16];
            *(float4*)&a[0]  = *(const float4*)&As[kk][ty * 16];
            *(float4*)&a[4]  = *(const float4*)&As[kk][ty * 16 + 4];
            *(float4*)&a[8]  = *(const float4*)&As[kk][ty * 16 + 8];
            *(float4*)&a[12] = *(const float4*)&As[kk][ty * 16 + 12];
            ulonglong2 bA = *(const ulonglong2*)&Bs[kk][tx * 8];
            ulonglong2 bB = *(const ulonglong2*)&Bs[kk][tx * 8 + 4];
#pragma unroll
            for (int i = 0; i < 16; i++) {
                unsigned long long a2 = pack2(a[i], a[i]);
                ffma2(acc[i][0], a2, bA.x);
                ffma2(acc[i][1], a2, bA.y);
                ffma2(acc[i][2], a2, bB.x);
                ffma2(acc[i][3], a2, bB.y);
            }
        }
    }

    // epilogue
    const int crow = row0 + ty * 16;
    const int ccol = col0 + tx * 8;
#pragma unroll
    for (int i = 0; i < 16; i++) {
        float v[8];
#pragma unroll
        for (int q = 0; q < 4; q++) {
            float2 p = unpack2(acc[i][q]);
            v[2 * q] = p.x; v[2 * q + 1] = p.y;
        }
        float* cp = C + (size_t)(crow + i) * NMAT + ccol;
        if (EPI == 0) {
#pragma unroll
            for (int q = 0; q < 8; q++) v[q] += e0[ccol + q];
        } else {
            float m = smask[ty * 16 + i];
#pragma unroll
            for (int q = 0; q < 8; q++) {
                int n = tx * 8 + q;
                v[q] = fmaxf(v[q] * ssc[n] + ssh[n], 0.0f) * m;
            }
        }
        *(float4*)cp       = make_float4(v[0], v[1], v[2], v[3]);
        *(float4*)(cp + 4) = make_float4(v[4], v[5], v[6], v[7]);
    }
}

// ---------------------------------------------------------------------------
// k4: lifted = relu(BN(gather(feat)@wl)) * nmask.
// ---------------------------------------------------------------------------
__global__ __launch_bounds__(256)
void lift_kernel(const float* __restrict__ feat, const int* __restrict__ idx,
                 const float* __restrict__ xyz, const float* __restrict__ wl,
                 const float* __restrict__ gamma_l, const float* __restrict__ beta_l,
                 const float* __restrict__ mean_l, const float* __restrict__ var_l,
                 float* __restrict__ L) {
    extern __shared__ float sm4[];
    float* As    = sm4;             // [64][256] transposed
    float* Bs    = sm4 + 16384;     // [64][64]
    float* smask = sm4 + 20480;     // [256]
    float* ssc   = sm4 + 20736;     // [64]
    float* ssh   = sm4 + 20800;     // [64]

    const int tid  = threadIdx.x;
    const int row0 = blockIdx.x * 256;

    {
        int grow = row0 + tid;
        int nbr  = idx[grow];
        int b    = grow >> 15;
        const float* np = xyz + ((size_t)(b << 11) + nbr) * 3;
        smask[tid] = (np[0] != 0.0f || np[1] != 0.0f || np[2] != 0.0f) ? 1.0f : 0.0f;
        if (tid < 64) {
            float sc = gamma_l[tid] * rsqrtf(var_l[tid] + BN_EPS);
            ssc[tid] = sc;
            ssh[tid] = beta_l[tid] - mean_l[tid] * sc;
        }
    }
    {
        int kr = tid >> 4;
        int cc = (tid & 15) * 4;
#pragma unroll
        for (int h2 = 0; h2 < 4; h2++)
            *(float4*)&Bs[(kr + h2 * 16) * 64 + cc] =
                *(const float4*)(wl + (size_t)(kr + h2 * 16) * 64 + cc);
    }
    {
        int cc = (tid & 15) * 4;
#pragma unroll
        for (int h2 = 0; h2 < 16; h2++) {
            int r    = (tid >> 4) + h2 * 16;
            int grow = row0 + r;
            int nbr  = idx[grow];
            int b    = grow >> 15;
            float4 f = *(const float4*)(feat + ((size_t)(b << 11) + nbr) * 64 + cc);
            As[(cc + 0) * 256 + r] = f.x;
            As[(cc + 1) * 256 + r] = f.y;
            As[(cc + 2) * 256 + r] = f.z;
            As[(cc + 3) * 256 + r] = f.w;
        }
    }
    __syncthreads();

    const int tx = tid & 7;
    const int ty = tid >> 3;
    unsigned long long acc[8][4];
#pragma unroll
    for (int i = 0; i < 8; i++)
#pragma unroll
        for (int q = 0; q < 4; q++) acc[i][q] = 0ull;

#pragma unroll 8
    for (int kk = 0; kk < 64; kk++) {
        float a[8];
        *(float4*)&a[0] = *(const float4*)&As[kk * 256 + ty * 8];
        *(float4*)&a[4] = *(const float4*)&As[kk * 256 + ty * 8 + 4];
        ulonglong2 bA = *(const ulonglong2*)&Bs[kk * 64 + tx * 8];
        ulonglong2 bB = *(const ulonglong2*)&Bs[kk * 64 + tx * 8 + 4];
#pragma unroll
        for (int i = 0; i < 8; i++) {
            unsigned long long a2 = pack2(a[i], a[i]);
            ffma2(acc[i][0], a2, bA.x);
            ffma2(acc[i][1], a2, bA.y);
            ffma2(acc[i][2], a2, bB.x);
            ffma2(acc[i][3], a2, bB.y);
        }
    }

#pragma unroll
    for (int i = 0; i < 8; i++) {
        int rloc = ty * 8 + i;
        int grow = row0 + rloc;
        float m  = smask[rloc];
        float v[8];
#pragma unroll
        for (int q = 0; q < 8; q++) {
            float2 p = unpack2(acc[i][q >> 1]);
            int n = tx * 8 + q;
            float x = ((q & 1) ? p.y : p.x) * ssc[n] + ssh[n];
            v[q] = fmaxf(x, 0.0f) * m;
        }
        float* cp = L + (size_t)grow * 64 + tx * 8;
        *(float4*)cp       = make_float4(v[0], v[1], v[2], v[3]);
        *(float4*)(cp + 4) = make_float4(v[4], v[5], v[6], v[7]);
    }
}

// ---------------------------------------------------------------------------
// k5: transformed[p][i][l] = sum_j X[p][i][j] * lifted[p][j][l].
// ---------------------------------------------------------------------------
__global__ __launch_bounds__(256)
void xform_kernel(const float* __restrict__ X, const float* __restrict__ L,
                  float* __restrict__ T) {
    extern __shared__ float sm5[];
    float* sX = sm5;            // 16*256
    float* sL = sm5 + 4096;     // 16*1024

    const int tid = threadIdx.x;
    const int g0  = blockIdx.x * 16;

    for (int e = tid * 4; e < 4096; e += 1024)
        *(float4*)&sX[e] = *(const float4*)(X + (size_t)g0 * 256 + e);
    for (int e = tid * 4; e < 16384; e += 1024)
        *(float4*)&sL[e] = *(const float4*)(L + (size_t)g0 * 1024 + e);
    __syncthreads();

    const int p = tid >> 4;
    const int i = tid & 15;

    float xr[16];
    {
        const float4* xp = (const float4*)&sX[p * 256 + i * 16];
#pragma unroll
        for (int q = 0; q < 4; q++) *(float4*)&xr[q * 4] = xp[q];
    }

    unsigned long long acc[32];
#pragma unroll
    for (int q = 0; q < 32; q++) acc[q] = 0ull;

#pragma unroll
    for (int j = 0; j < 16; j++) {
        unsigned long long xv = pack2(xr[j], xr[j]);
        const ulonglong2* lp = (const ulonglong2*)&sL[p * 1024 + j * 64];
#pragma unroll
        for (int q = 0; q < 16; q++) {
            ulonglong2 lv = lp[q];
            ffma2(acc[2 * q],     xv, lv.x);
            ffma2(acc[2 * q + 1], xv, lv.y);
        }
    }

    float* dst = T + (size_t)(g0 + p) * 1024 + i * 64;
#pragma unroll
    for (int q = 0; q < 16; q++) {
        float2 a = unpack2(acc[2 * q]);
        float2 b2v = unpack2(acc[2 * q + 1]);
        *(float4*)(dst + q * 4) = make_float4(a.x, a.y, b2v.x, b2v.y);
    }
}

// ---------------------------------------------------------------------------
extern "C" void kernel_launch(void* const* d_in, const int* in_sizes, int n_in,
                              void* d_out, int out_size) {
    const float* xyz     = (const float*)d_in[0];
    const float* feat    = (const float*)d_in[1];
    const float* w1      = (const float*)d_in[2];
    const float* b1      = (const float*)d_in[3];
    const float* gamma1  = (const float*)d_in[4];
    const float* beta1   = (const float*)d_in[5];
    const float* mean1   = (const float*)d_in[6];
    const float* var1    = (const float*)d_in[7];
    const float* w2      = (const float*)d_in[8];
    const float* b2      = (const float*)d_in[9];
    const float* wl      = (const float*)d_in[10];
    const float* gamma_l = (const float*)d_in[11];
    const float* beta_l  = (const float*)d_in[12];
    const float* mean_l  = (const float*)d_in[13];
    const float* var_l   = (const float*)d_in[14];
    const float* wf      = (const float*)d_in[15];
    const float* gamma_f = (const float*)d_in[16];
    const float* beta_f  = (const float*)d_in[17];
    const float* mean_f  = (const float*)d_in[18];
    const float* var_f   = (const float*)d_in[19];
    float* out = (float*)d_out;

    float *pd_ptr, *h_ptr, *X_ptr, *L_ptr, *T_ptr;
    int *pi_ptr, *idx_ptr;
    cudaGetSymbolAddress((void**)&pd_ptr, g_pd);
    cudaGetSymbolAddress((void**)&pi_ptr, g_pi);
    cudaGetSymbolAddress((void**)&idx_ptr, g_idx);
    cudaGetSymbolAddress((void**)&h_ptr, g_h);
    cudaGetSymbolAddress((void**)&X_ptr, g_X);
    cudaGetSymbolAddress((void**)&L_ptr, g_lift);
    cudaGetSymbolAddress((void**)&T_ptr, g_tr);

    knn_part<<<(NPTS / 128) * SPLIT, 128>>>(xyz, pd_ptr, pi_ptr);
    knn_merge<<<NPTS / 128, 128>>>(pd_ptr, pi_ptr, idx_ptr);

    h_kernel<<<NPTS / 16, 256>>>(xyz, idx_ptr, w1, b1, gamma1, beta1,
                                 mean1, var1, h_ptr);

    // k3: X = h @ w2 + b2   (M=16384, N=256, K=512) 128x128 tiles, 128 thr
    sgemm3<256, 512, 0><<<dim3(NPTS / 128, 2), 128>>>(
        h_ptr, w2, b2, nullptr, nullptr, nullptr, xyz, X_ptr);

    // k4: lifted
    cudaFuncSetAttribute(lift_kernel,
                         cudaFuncAttributeMaxDynamicSharedMemorySize, 83456);
    lift_kernel<<<NPTS * 16 / 256, 256, 83456>>>(
        feat, idx_ptr, xyz, wl, gamma_l, beta_l, mean_l, var_l, L_ptr);

    // k5: transformed
    cudaFuncSetAttribute(xform_kernel,
                         cudaFuncAttributeMaxDynamicSharedMemorySize, 81920);
    xform_kernel<<<NPTS / 16, 256, 81920>>>(X_ptr, L_ptr, T_ptr);

    // k6: out = relu(BN(tr @ wf)) * qmask  (M=16384, N=128, K=1024)
    sgemm3<128, 1024, 1><<<dim3(NPTS / 128, 1), 128>>>(
        T_ptr, wf, gamma_f, beta_f, mean_f, var_f, xyz, out);
}

// round 8
// speedup vs baseline: 1.3196x; 1.3196x over previous
#include <cuda_runtime.h>
#include <cuda_bf16.h>
#include <cstdint>
#include <float.h>

#define BB    8
#define NN    2048
#define KK    16
#define CIN   64
#define COUT  128
#define BN_EPS 1e-3f
#define LARGE_DIST 1e9f

#define SPLIT 8
#define CAND  (NN / SPLIT)   // 256
#define NPTS  (BB * NN)      // 16384

// ---- global scratch -------------------------------------------------------
__device__ float          g_pd[NPTS * SPLIT * KK];
__device__ int            g_pi[NPTS * SPLIT * KK];
__device__ int            g_idx[NPTS * KK];
__device__ unsigned short g_h_hi[(size_t)NPTS * 512];
__device__ unsigned short g_h_lo[(size_t)NPTS * 512];
__device__ float          g_X[(size_t)NPTS * 256];
__device__ float          g_lift[(size_t)NPTS * 16 * 64];
__device__ unsigned short g_t_hi[(size_t)NPTS * 1024];
__device__ unsigned short g_t_lo[(size_t)NPTS * 1024];
__device__ unsigned short g_w2t_hi[256 * 512];
__device__ unsigned short g_w2t_lo[256 * 512];
__device__ unsigned short g_wft_hi[128 * 1024];
__device__ unsigned short g_wft_lo[128 * 1024];

// ---- packed fp32x2 helpers ------------------------------------------------
__device__ __forceinline__ unsigned long long pack2(float lo, float hi) {
    unsigned long long r;
    asm("mov.b64 %0, {%1, %2};" : "=l"(r) : "f"(lo), "f"(hi));
    return r;
}
__device__ __forceinline__ float2 unpack2(unsigned long long v) {
    float2 r;
    asm("mov.b64 {%0, %1}, %2;" : "=f"(r.x), "=f"(r.y) : "l"(v));
    return r;
}
__device__ __forceinline__ void ffma2(unsigned long long& a,
                                      unsigned long long x,
                                      unsigned long long y) {
    asm("fma.rn.f32x2 %0, %1, %2, %0;" : "+l"(a) : "l"(x), "l"(y));
}
__device__ __forceinline__ unsigned long long add2(unsigned long long x,
                                                   unsigned long long y) {
    unsigned long long r;
    asm("add.rn.f32x2 %0, %1, %2;" : "=l"(r) : "l"(x), "l"(y));
    return r;
}
__device__ __forceinline__ unsigned long long mul2(unsigned long long x,
                                                   unsigned long long y) {
    unsigned long long r;
    asm("mul.rn.f32x2 %0, %1, %2;" : "=l"(r) : "l"(x), "l"(y));
    return r;
}

// ---- mma.sync helpers ------------------------------------------------------
__device__ __forceinline__ uint32_t smem_u32(const void* p) {
    uint32_t a;
    asm("{ .reg .u64 t; cvta.to.shared.u64 t, %1; cvt.u32.u64 %0, t; }"
        : "=r"(a) : "l"(p));
    return a;
}
__device__ __forceinline__ void ldm_x4(uint32_t* r, uint32_t addr) {
    asm volatile("ldmatrix.sync.aligned.m8n8.x4.shared.b16 {%0,%1,%2,%3}, [%4];"
                 : "=r"(r[0]), "=r"(r[1]), "=r"(r[2]), "=r"(r[3]) : "r"(addr));
}
__device__ __forceinline__ void ldm_x2(uint32_t* r, uint32_t addr) {
    asm volatile("ldmatrix.sync.aligned.m8n8.x2.shared.b16 {%0,%1}, [%2];"
                 : "=r"(r[0]), "=r"(r[1]) : "r"(addr));
}
__device__ __forceinline__ void mma_bf16(float* d, const uint32_t* a,
                                         const uint32_t* b) {
    asm volatile(
        "mma.sync.aligned.m16n8k16.row.col.f32.bf16.bf16.f32 "
        "{%0,%1,%2,%3}, {%4,%5,%6,%7}, {%8,%9}, {%0,%1,%2,%3};"
        : "+f"(d[0]), "+f"(d[1]), "+f"(d[2]), "+f"(d[3])
        : "r"(a[0]), "r"(a[1]), "r"(a[2]), "r"(a[3]), "r"(b[0]), "r"(b[1]));
}

// ---------------------------------------------------------------------------
// KNN
// ---------------------------------------------------------------------------
__device__ __forceinline__ void insert16(float* bd, int* bi, float d, int j) {
    bd[KK - 1] = d; bi[KK - 1] = j;
#pragma unroll
    for (int t = KK - 1; t > 0; --t) {
        if (bd[t] < bd[t - 1]) {
            float td = bd[t]; bd[t] = bd[t - 1]; bd[t - 1] = td;
            int   ti = bi[t]; bi[t] = bi[t - 1]; bi[t - 1] = ti;
        }
    }
}

__global__ __launch_bounds__(128)
void knn_part(const float* __restrict__ xyz,
              float* __restrict__ pd, int* __restrict__ pi) {
    __shared__ float s_nx[NN], s_ny[NN], s_nz[NN], s_pen[NN];
    const int tid = threadIdx.x;
    const int qg  = blockIdx.x >> 3;
    const int sp  = blockIdx.x & 7;
    const int g   = qg * 128 + tid;
    const int b   = g >> 11;
    const int n   = g & (NN - 1);

    for (int j = tid; j < NN; j += 128) {
        const float* p = xyz + ((size_t)b * NN + j) * 3;
        float x = p[0], y = p[1], z = p[2];
        bool v = (x != 0.0f || y != 0.0f || z != 0.0f);
        s_nx[j] = -x; s_ny[j] = -y; s_nz[j] = -z;
        s_pen[j] = v ? 0.0f : LARGE_DIST;
    }
    __syncthreads();

    const float* qp = xyz + ((size_t)b * NN + n) * 3;
    unsigned long long qx2 = pack2(qp[0], qp[0]);
    unsigned long long qy2 = pack2(qp[1], qp[1]);
    unsigned long long qz2 = pack2(qp[2], qp[2]);

    float bd[KK]; int bi[KK];
#pragma unroll
    for (int t = 0; t < KK; t++) { bd[t] = FLT_MAX; bi[t] = 0; }

    const unsigned long long* px2 = (const unsigned long long*)s_nx + sp * (CAND / 2);
    const unsigned long long* py2 = (const unsigned long long*)s_ny + sp * (CAND / 2);
    const unsigned long long* pz2 = (const unsigned long long*)s_nz + sp * (CAND / 2);
    const unsigned long long* pp2 = (const unsigned long long*)s_pen + sp * (CAND / 2);
    const int jbase = sp * CAND;

#pragma unroll 8
    for (int jj = 0; jj < CAND / 2; jj++) {
        unsigned long long dx2 = add2(qx2, px2[jj]);
        unsigned long long dy2 = add2(qy2, py2[jj]);
        unsigned long long dz2 = add2(qz2, pz2[jj]);
        unsigned long long d2  = mul2(dx2, dx2);
        ffma2(d2, dy2, dy2);
        ffma2(d2, dz2, dz2);
        d2 = add2(d2, pp2[jj]);
        float2 d = unpack2(d2);
        if (fminf(d.x, d.y) < bd[KK - 1]) {
            if (d.x < bd[KK - 1]) insert16(bd, bi, d.x, jbase + 2 * jj);
            if (d.y < bd[KK - 1]) insert16(bd, bi, d.y, jbase + 2 * jj + 1);
        }
    }

    float* po = pd + ((size_t)g * SPLIT + sp) * KK;
    int*   io = pi + ((size_t)g * SPLIT + sp) * KK;
#pragma unroll
    for (int t = 0; t < KK; t++) { po[t] = bd[t]; io[t] = bi[t]; }
}

__global__ __launch_bounds__(128)
void knn_merge(const float* __restrict__ pd, const int* __restrict__ pi,
               int* __restrict__ idx_out) {
    const int g = blockIdx.x * 128 + threadIdx.x;
    float bd[KK]; int bi[KK];
#pragma unroll
    for (int t = 0; t < KK; t++) { bd[t] = FLT_MAX; bi[t] = 0; }
    const float* pp = pd + (size_t)g * SPLIT * KK;
    const int*   ii = pi + (size_t)g * SPLIT * KK;
    for (int c = 0; c < SPLIT * KK; c++) {
        float d = pp[c];
        if (d < bd[KK - 1]) insert16(bd, bi, d, ii[c]);
    }
#pragma unroll
    for (int t = 0; t < KK; t++) idx_out[(size_t)g * KK + t] = bi[t];
}

// ---------------------------------------------------------------------------
// k2: h precompute -> bf16 hi/lo
// ---------------------------------------------------------------------------
__global__ __launch_bounds__(256)
void h_kernel(const float* __restrict__ xyz, const int* __restrict__ idx,
              const float* __restrict__ w1, const float* __restrict__ b1,
              const float* __restrict__ gamma1, const float* __restrict__ beta1,
              const float* __restrict__ mean1, const float* __restrict__ var1,
              unsigned short* __restrict__ Hhi, unsigned short* __restrict__ Hlo) {
    __shared__ float sw[96], sb[32], ssc[32], ssh[32];
    const int tid = threadIdx.x;
    if (tid < 96) sw[tid] = w1[tid];
    if (tid < 32) {
        sb[tid] = b1[tid];
        float sc = gamma1[tid] * rsqrtf(var1[tid] + BN_EPS);
        ssc[tid] = sc;
        ssh[tid] = beta1[tid] - mean1[tid] * sc;
    }
    __syncthreads();

    const int g0 = blockIdx.x * 16;
    const int p  = tid >> 4;
    const int k  = tid & 15;
    const int g  = g0 + p;
    const int b  = g >> 11;
    const int n  = g & (NN - 1);
    const int nbr = idx[(size_t)g * KK + k];

    const float* qp = xyz + ((size_t)b * NN + n) * 3;
    const float* np = xyz + ((size_t)b * NN + nbr) * 3;
    float qx = qp[0], qy = qp[1], qz = qp[2];
    float px = np[0], py = np[1], pz = np[2];
    float nm = (px != 0.0f || py != 0.0f || pz != 0.0f) ? 1.0f : 0.0f;
    float r0 = nm * (px - qx), r1 = nm * (py - qy), r2 = nm * (pz - qz);

    unsigned short hh[32], ll[32];
#pragma unroll
    for (int d = 0; d < 32; d++) {
        float v = r0 * sw[d] + r1 * sw[32 + d] + r2 * sw[64 + d] + sb[d];
        v = fmaxf(v, 0.0f);
        v = v * ssc[d] + ssh[d];
        __nv_bfloat16 hv = __float2bfloat16(v);
        float res = v - __bfloat162float(hv);
        hh[d] = __bfloat16_as_ushort(hv);
        ll[d] = __bfloat16_as_ushort(__float2bfloat16(res));
    }
    size_t off = (size_t)g * 512 + k * 32;
#pragma unroll
    for (int q = 0; q < 4; q++) {
        *(uint4*)(Hhi + off + q * 8) = *(uint4*)&hh[q * 8];
        *(uint4*)(Hlo + off + q * 8) = *(uint4*)&ll[q * 8];
    }
}

// ---------------------------------------------------------------------------
// prep: transpose + bf16-split a weight matrix  W[K][N] -> out[N][K]
// ---------------------------------------------------------------------------
__global__ void prep_bT(const float* __restrict__ W,
                        unsigned short* __restrict__ hi,
                        unsigned short* __restrict__ lo, int K, int N) {
    int i = blockIdx.x * 256 + threadIdx.x;
    if (i >= K * N) return;
    int n = i % N, k = i / N;
    float v = W[i];
    __nv_bfloat16 h = __float2bfloat16(v);
    float r = v - __bfloat162float(h);
    hi[(size_t)n * K + k] = __bfloat16_as_ushort(h);
    lo[(size_t)n * K + k] = __bfloat16_as_ushort(__float2bfloat16(r));
}

// ---------------------------------------------------------------------------
// mma.sync bf16 3-term GEMM: C[16384 x NMAT] = A[16384 x KTOT] @ BT^T
// BT is [NMAT][KTOT] (hi/lo).  CTA: BM x 128.  8 warps: 2 x 4, warp tile
// (BM/2) x 32.  EPI 0: +bias   EPI 1: relu(BN)*qmask.
// ---------------------------------------------------------------------------
template<int BM, int NMAT, int KTOT, int EPI>
__global__ __launch_bounds__(256)
void mma_gemm(const unsigned short* __restrict__ Ahi,
              const unsigned short* __restrict__ Alo,
              const unsigned short* __restrict__ Bhi,
              const unsigned short* __restrict__ Blo,
              const float* __restrict__ e0, const float* __restrict__ e1,
              const float* __restrict__ e2, const float* __restrict__ e3,
              const float* __restrict__ xyz, float* __restrict__ C) {
    constexpr int MT = BM / 32;          // m16-tiles per warp
    constexpr int LDS_H = 40;            // smem row pitch in halves
    __shared__ __align__(16) unsigned short sAh[BM * LDS_H];
    __shared__ __align__(16) unsigned short sAl[BM * LDS_H];
    __shared__ __align__(16) unsigned short sBh[128 * LDS_H];
    __shared__ __align__(16) unsigned short sBl[128 * LDS_H];

    const int tid  = threadIdx.x;
    const int lane = tid & 31;
    const int wid  = tid >> 5;
    const int wr   = wid >> 2;           // 0..1
    const int wc   = wid & 3;            // 0..3
    const int g0   = blockIdx.x * BM;
    const int col0 = blockIdx.y * 128;

    const uint32_t aHiB = smem_u32(sAh), aLoB = smem_u32(sAl);
    const uint32_t bHiB = smem_u32(sBh), bLoB = smem_u32(sBl);

    float acc[MT][4][4];
#pragma unroll
    for (int m = 0; m < MT; m++)
#pragma unroll
        for (int n = 0; n < 4; n++)
#pragma unroll
            for (int q = 0; q < 4; q++) acc[m][n][q] = 0.0f;

    const int q8 = lane >> 3;            // 0..3
    const int r8 = lane & 7;

    for (int k0 = 0; k0 < KTOT; k0 += 32) {
        // load A tiles (BM x 32 halves each)
#pragma unroll
        for (int v = tid; v < BM * 4; v += 256) {
            int row = v >> 2, c8 = (v & 3) * 8;
            int dst = row * LDS_H + c8;
            size_t src = (size_t)(g0 + row) * KTOT + k0 + c8;
            *(uint4*)(sAh + dst) = *(const uint4*)(Ahi + src);
            *(uint4*)(sAl + dst) = *(const uint4*)(Alo + src);
        }
        // load B tiles (128 x 32 halves each)
#pragma unroll
        for (int v = tid; v < 512; v += 256) {
            int row = v >> 2, c8 = (v & 3) * 8;
            int dst = row * LDS_H + c8;
            size_t src = (size_t)(col0 + row) * KTOT + k0 + c8;
            *(uint4*)(sBh + dst) = *(const uint4*)(Bhi + src);
            *(uint4*)(sBl + dst) = *(const uint4*)(Blo + src);
        }
        __syncthreads();

#pragma unroll
        for (int ks = 0; ks < 2; ks++) {
            const int kk = ks * 16;
            uint32_t ah[MT][4], al[MT][4];
#pragma unroll
            for (int m = 0; m < MT; m++) {
                int arow = wr * (BM / 2) + m * 16 + (q8 & 1) * 8 + r8;
                int acol = kk + (q8 >> 1) * 8;
                uint32_t off = (uint32_t)(arow * LDS_H + acol) * 2;
                ldm_x4(ah[m], aHiB + off);
                ldm_x4(al[m], aLoB + off);
            }
            uint32_t bh[4][2], bl[4][2];
#pragma unroll
            for (int n = 0; n < 4; n++) {
                int nrow = wc * 32 + n * 8 + r8;
                int ncol = kk + (q8 & 1) * 8;
                uint32_t off = (uint32_t)(nrow * LDS_H + ncol) * 2;
                ldm_x2(bh[n], bHiB + off);
                ldm_x2(bl[n], bLoB + off);
            }
#pragma unroll
            for (int m = 0; m < MT; m++)
#pragma unroll
                for (int n = 0; n < 4; n++) {
                    mma_bf16(acc[m][n], ah[m], bh[n]);
                    mma_bf16(acc[m][n], ah[m], bl[n]);
                    mma_bf16(acc[m][n], al[m], bh[n]);
                }
        }
        __syncthreads();
    }

    // epilogue: d0,d1 -> (row, col..col+1), d2,d3 -> (row+8)
#pragma unroll
    for (int m = 0; m < MT; m++) {
        int r1 = g0 + wr * (BM / 2) + m * 16 + (lane >> 2);
        int r2 = r1 + 8;
        float m1 = 1.0f, m2 = 1.0f;
        if (EPI == 1) {
            const float* p1 = xyz + (size_t)r1 * 3;
            const float* p2 = xyz + (size_t)r2 * 3;
            m1 = (p1[0] != 0.0f || p1[1] != 0.0f || p1[2] != 0.0f) ? 1.0f : 0.0f;
            m2 = (p2[0] != 0.0f || p2[1] != 0.0f || p2[2] != 0.0f) ? 1.0f : 0.0f;
        }
#pragma unroll
        for (int n = 0; n < 4; n++) {
            int c = col0 + wc * 32 + n * 8 + (lane & 3) * 2;
            float v0 = acc[m][n][0], v1 = acc[m][n][1];
            float v2 = acc[m][n][2], v3 = acc[m][n][3];
            if (EPI == 0) {
                float bb0 = e0[c], bb1 = e0[c + 1];
                v0 += bb0; v1 += bb1; v2 += bb0; v3 += bb1;
            } else {
                float sc0 = e0[c] * rsqrtf(e3[c] + BN_EPS);
                float sh0 = e1[c] - e2[c] * sc0;
                float sc1 = e0[c + 1] * rsqrtf(e3[c + 1] + BN_EPS);
                float sh1 = e1[c + 1] - e2[c + 1] * sc1;
                v0 = fmaxf(v0 * sc0 + sh0, 0.0f) * m1;
                v1 = fmaxf(v1 * sc1 + sh1, 0.0f) * m1;
                v2 = fmaxf(v2 * sc0 + sh0, 0.0f) * m2;
                v3 = fmaxf(v3 * sc1 + sh1, 0.0f) * m2;
            }
            *(float2*)(C + (size_t)r1 * NMAT + c) = make_float2(v0, v1);
            *(float2*)(C + (size_t)r2 * NMAT + c) = make_float2(v2, v3);
        }
    }
}

// ---------------------------------------------------------------------------
// k4: lifted = relu(BN(gather(feat)@wl)) * nmask.
// ---------------------------------------------------------------------------
__global__ __launch_bounds__(256)
void lift_kernel(const float* __restrict__ feat, const int* __restrict__ idx,
                 const float* __restrict__ xyz, const float* __restrict__ wl,
                 const float* __restrict__ gamma_l, const float* __restrict__ beta_l,
                 const float* __restrict__ mean_l, const float* __restrict__ var_l,
                 float* __restrict__ L) {
    extern __shared__ float sm4[];
    float* As    = sm4;             // [64][256] transposed
    float* Bs    = sm4 + 16384;     // [64][64]
    float* smask = sm4 + 20480;     // [256]
    float* ssc   = sm4 + 20736;     // [64]
    float* ssh   = sm4 + 20800;     // [64]

    const int tid  = threadIdx.x;
    const int row0 = blockIdx.x * 256;

    {
        int grow = row0 + tid;
        int nbr  = idx[grow];
        int b    = grow >> 15;
        const float* np = xyz + ((size_t)(b << 11) + nbr) * 3;
        smask[tid] = (np[0] != 0.0f || np[1] != 0.0f || np[2] != 0.0f) ? 1.0f : 0.0f;
        if (tid < 64) {
            float sc = gamma_l[tid] * rsqrtf(var_l[tid] + BN_EPS);
            ssc[tid] = sc;
            ssh[tid] = beta_l[tid] - mean_l[tid] * sc;
        }
    }
    {
        int kr = tid >> 4;
        int cc = (tid & 15) * 4;
#pragma unroll
        for (int h2 = 0; h2 < 4; h2++)
            *(float4*)&Bs[(kr + h2 * 16) * 64 + cc] =
                *(const float4*)(wl + (size_t)(kr + h2 * 16) * 64 + cc);
    }
    {
        int cc = (tid & 15) * 4;
#pragma unroll
        for (int h2 = 0; h2 < 16; h2++) {
            int r    = (tid >> 4) + h2 * 16;
            int grow = row0 + r;
            int nbr  = idx[grow];
            int b    = grow >> 15;
            float4 f = *(const float4*)(feat + ((size_t)(b << 11) + nbr) * 64 + cc);
            As[(cc + 0) * 256 + r] = f.x;
            As[(cc + 1) * 256 + r] = f.y;
            As[(cc + 2) * 256 + r] = f.z;
            As[(cc + 3) * 256 + r] = f.w;
        }
    }
    __syncthreads();

    const int tx = tid & 7;
    const int ty = tid >> 3;
    unsigned long long acc[8][4];
#pragma unroll
    for (int i = 0; i < 8; i++)
#pragma unroll
        for (int q = 0; q < 4; q++) acc[i][q] = 0ull;

#pragma unroll 8
    for (int kk = 0; kk < 64; kk++) {
        float a[8];
        *(float4*)&a[0] = *(const float4*)&As[kk * 256 + ty * 8];
        *(float4*)&a[4] = *(const float4*)&As[kk * 256 + ty * 8 + 4];
        ulonglong2 bA = *(const ulonglong2*)&Bs[kk * 64 + tx * 8];
        ulonglong2 bB = *(const ulonglong2*)&Bs[kk * 64 + tx * 8 + 4];
#pragma unroll
        for (int i = 0; i < 8; i++) {
            unsigned long long a2 = pack2(a[i], a[i]);
            ffma2(acc[i][0], a2, bA.x);
            ffma2(acc[i][1], a2, bA.y);
            ffma2(acc[i][2], a2, bB.x);
            ffma2(acc[i][3], a2, bB.y);
        }
    }

#pragma unroll
    for (int i = 0; i < 8; i++) {
        int rloc = ty * 8 + i;
        int grow = row0 + rloc;
        float m  = smask[rloc];
        float v[8];
#pragma unroll
        for (int q = 0; q < 8; q++) {
            float2 p = unpack2(acc[i][q >> 1]);
            int n = tx * 8 + q;
            float x = ((q & 1) ? p.y : p.x) * ssc[n] + ssh[n];
            v[q] = fmaxf(x, 0.0f) * m;
        }
        float* cp = L + (size_t)grow * 64 + tx * 8;
        *(float4*)cp       = make_float4(v[0], v[1], v[2], v[3]);
        *(float4*)(cp + 4) = make_float4(v[4], v[5], v[6], v[7]);
    }
}

// ---------------------------------------------------------------------------
// k5: transformed = X @ lifted, output bf16 hi/lo.
// ---------------------------------------------------------------------------
__global__ __launch_bounds__(256)
void xform_kernel(const float* __restrict__ X, const float* __restrict__ L,
                  unsigned short* __restrict__ Thi,
                  unsigned short* __restrict__ Tlo) {
    extern __shared__ float sm5[];
    float* sX = sm5;            // 16*256
    float* sL = sm5 + 4096;     // 16*1024

    const int tid = threadIdx.x;
    const int g0  = blockIdx.x * 16;

    for (int e = tid * 4; e < 4096; e += 1024)
        *(float4*)&sX[e] = *(const float4*)(X + (size_t)g0 * 256 + e);
    for (int e = tid * 4; e < 16384; e += 1024)
        *(float4*)&sL[e] = *(const float4*)(L + (size_t)g0 * 1024 + e);
    __syncthreads();

    const int p = tid >> 4;
    const int i = tid & 15;

    float xr[16];
    {
        const float4* xp = (const float4*)&sX[p * 256 + i * 16];
#pragma unroll
        for (int q = 0; q < 4; q++) *(float4*)&xr[q * 4] = xp[q];
    }

    unsigned long long acc[32];
#pragma unroll
    for (int q = 0; q < 32; q++) acc[q] = 0ull;

#pragma unroll
    for (int j = 0; j < 16; j++) {
        unsigned long long xv = pack2(xr[j], xr[j]);
        const ulonglong2* lp = (const ulonglong2*)&sL[p * 1024 + j * 64];
#pragma unroll
        for (int q = 0; q < 16; q++) {
            ulonglong2 lv = lp[q];
            ffma2(acc[2 * q],     xv, lv.x);
            ffma2(acc[2 * q + 1], xv, lv.y);
        }
    }

    unsigned short hh[64], ll[64];
#pragma unroll
    for (int q = 0; q < 32; q++) {
        float2 a = unpack2(acc[q]);
        __nv_bfloat16 h0 = __float2bfloat16(a.x);
        __nv_bfloat16 h1 = __float2bfloat16(a.y);
        hh[2 * q]     = __bfloat16_as_ushort(h0);
        hh[2 * q + 1] = __bfloat16_as_ushort(h1);
        ll[2 * q]     = __bfloat16_as_ushort(__float2bfloat16(a.x - __bfloat162float(h0)));
        ll[2 * q + 1] = __bfloat16_as_ushort(__float2bfloat16(a.y - __bfloat162float(h1)));
    }
    size_t off = (size_t)(g0 + p) * 1024 + i * 64;
#pragma unroll
    for (int q = 0; q < 8; q++) {
        *(uint4*)(Thi + off + q * 8) = *(uint4*)&hh[q * 8];
        *(uint4*)(Tlo + off + q * 8) = *(uint4*)&ll[q * 8];
    }
}

// ---------------------------------------------------------------------------
extern "C" void kernel_launch(void* const* d_in, const int* in_sizes, int n_in,
                              void* d_out, int out_size) {
    const float* xyz     = (const float*)d_in[0];
    const float* feat    = (const float*)d_in[1];
    const float* w1      = (const float*)d_in[2];
    const float* b1      = (const float*)d_in[3];
    const float* gamma1  = (const float*)d_in[4];
    const float* beta1   = (const float*)d_in[5];
    const float* mean1   = (const float*)d_in[6];
    const float* var1    = (const float*)d_in[7];
    const float* w2      = (const float*)d_in[8];
    const float* b2      = (const float*)d_in[9];
    const float* wl      = (const float*)d_in[10];
    const float* gamma_l = (const float*)d_in[11];
    const float* beta_l  = (const float*)d_in[12];
    const float* mean_l  = (const float*)d_in[13];
    const float* var_l   = (const float*)d_in[14];
    const float* wf      = (const float*)d_in[15];
    const float* gamma_f = (const float*)d_in[16];
    const float* beta_f  = (const float*)d_in[17];
    const float* mean_f  = (const float*)d_in[18];
    const float* var_f   = (const float*)d_in[19];
    float* out = (float*)d_out;

    float *pd_ptr, *X_ptr, *L_ptr;
    int *pi_ptr, *idx_ptr;
    unsigned short *hhi, *hlo, *thi, *tlo, *w2hi, *w2lo, *wfhi, *wflo;
    cudaGetSymbolAddress((void**)&pd_ptr, g_pd);
    cudaGetSymbolAddress((void**)&pi_ptr, g_pi);
    cudaGetSymbolAddress((void**)&idx_ptr, g_idx);
    cudaGetSymbolAddress((void**)&hhi, g_h_hi);
    cudaGetSymbolAddress((void**)&hlo, g_h_lo);
    cudaGetSymbolAddress((void**)&X_ptr, g_X);
    cudaGetSymbolAddress((void**)&L_ptr, g_lift);
    cudaGetSymbolAddress((void**)&thi, g_t_hi);
    cudaGetSymbolAddress((void**)&tlo, g_t_lo);
    cudaGetSymbolAddress((void**)&w2hi, g_w2t_hi);
    cudaGetSymbolAddress((void**)&w2lo, g_w2t_lo);
    cudaGetSymbolAddress((void**)&wfhi, g_wft_hi);
    cudaGetSymbolAddress((void**)&wflo, g_wft_lo);

    knn_part<<<(NPTS / 128) * SPLIT, 128>>>(xyz, pd_ptr, pi_ptr);
    prep_bT<<<(512 * 256 + 255) / 256, 256>>>(w2, w2hi, w2lo, 512, 256);
    prep_bT<<<(1024 * 128 + 255) / 256, 256>>>(wf, wfhi, wflo, 1024, 128);
    knn_merge<<<NPTS / 128, 128>>>(pd_ptr, pi_ptr, idx_ptr);

    h_kernel<<<NPTS / 16, 256>>>(xyz, idx_ptr, w1, b1, gamma1, beta1,
                                 mean1, var1, hhi, hlo);

    // k3: X = h @ w2 + b2   (mma.sync bf16, grid 128x2)
    mma_gemm<128, 256, 512, 0><<<dim3(NPTS / 128, 2), 256>>>(
        hhi, hlo, w2hi, w2lo, b2, nullptr, nullptr, nullptr, xyz, X_ptr);

    cudaFuncSetAttribute(lift_kernel,
                         cudaFuncAttributeMaxDynamicSharedMemorySize, 83456);
    lift_kernel<<<NPTS * 16 / 256, 256, 83456>>>(
        feat, idx_ptr, xyz, wl, gamma_l, beta_l, mean_l, var_l, L_ptr);

    cudaFuncSetAttribute(xform_kernel,
                         cudaFuncAttributeMaxDynamicSharedMemorySize, 81920);
    xform_kernel<<<NPTS / 16, 256, 81920>>>(X_ptr, L_ptr, thi, tlo);

    // k6: out = relu(BN(tr @ wf)) * qmask   (mma.sync bf16, grid 256)
    mma_gemm<64, 128, 1024, 1><<<dim3(NPTS / 64, 1), 256>>>(
        thi, tlo, wfhi, wflo, gamma_f, beta_f, mean_f, var_f, xyz, out);
}

// round 10
// speedup vs baseline: 1.4675x; 1.1121x over previous
#include <cuda_runtime.h>
#include <cuda_bf16.h>
#include <cstdint>
#include <float.h>

#define BB    8
#define NN    2048
#define KK    16
#define CIN   64
#define COUT  128
#define BN_EPS 1e-3f
#define LARGE_DIST 1e9f
#define MARGIN 2e-4f

#define SPLIT 4
#define CAND  (NN / SPLIT)   // 512
#define NPTS  (BB * NN)      // 16384

// ---- global scratch -------------------------------------------------------
__device__ float          g_pd[NPTS * SPLIT * KK];
__device__ int            g_pi[NPTS * SPLIT * KK];
__device__ int            g_idx[NPTS * KK];
__device__ unsigned short g_h_hi[(size_t)NPTS * 512];
__device__ unsigned short g_h_lo[(size_t)NPTS * 512];
__device__ float          g_X[(size_t)NPTS * 256];
__device__ unsigned short g_t_hi[(size_t)NPTS * 1024];
__device__ unsigned short g_t_lo[(size_t)NPTS * 1024];
__device__ unsigned short g_w2t_hi[256 * 512];
__device__ unsigned short g_w2t_lo[256 * 512];
__device__ unsigned short g_wft_hi[128 * 1024];
__device__ unsigned short g_wft_lo[128 * 1024];

// ---- packed fp32x2 helpers ------------------------------------------------
__device__ __forceinline__ unsigned long long pack2(float lo, float hi) {
    unsigned long long r;
    asm("mov.b64 %0, {%1, %2};" : "=l"(r) : "f"(lo), "f"(hi));
    return r;
}
__device__ __forceinline__ float2 unpack2(unsigned long long v) {
    float2 r;
    asm("mov.b64 {%0, %1}, %2;" : "=f"(r.x), "=f"(r.y) : "l"(v));
    return r;
}
__device__ __forceinline__ void ffma2(unsigned long long& a,
                                      unsigned long long x,
                                      unsigned long long y) {
    asm("fma.rn.f32x2 %0, %1, %2, %0;" : "+l"(a) : "l"(x), "l"(y));
}

// ---- mma.sync helpers ------------------------------------------------------
__device__ __forceinline__ uint32_t smem_u32(const void* p) {
    uint32_t a;
    asm("{ .reg .u64 t; cvta.to.shared.u64 t, %1; cvt.u32.u64 %0, t; }"
        : "=r"(a) : "l"(p));
    return a;
}
__device__ __forceinline__ void ldm_x4(uint32_t* r, uint32_t addr) {
    asm volatile("ldmatrix.sync.aligned.m8n8.x4.shared.b16 {%0,%1,%2,%3}, [%4];"
                 : "=r"(r[0]), "=r"(r[1]), "=r"(r[2]), "=r"(r[3]) : "r"(addr));
}
__device__ __forceinline__ void ldm_x2(uint32_t* r, uint32_t addr) {
    asm volatile("ldmatrix.sync.aligned.m8n8.x2.shared.b16 {%0,%1}, [%2];"
                 : "=r"(r[0]), "=r"(r[1]) : "r"(addr));
}
__device__ __forceinline__ void mma_bf16(float* d, const uint32_t* a,
                                         const uint32_t* b) {
    asm volatile(
        "mma.sync.aligned.m16n8k16.row.col.f32.bf16.bf16.f32 "
        "{%0,%1,%2,%3}, {%4,%5,%6,%7}, {%8,%9}, {%0,%1,%2,%3};"
        : "+f"(d[0]), "+f"(d[1]), "+f"(d[2]), "+f"(d[3])
        : "r"(a[0]), "r"(a[1]), "r"(a[2]), "r"(a[3]), "r"(b[0]), "r"(b[1]));
}

// ---------------------------------------------------------------------------
// KNN
// ---------------------------------------------------------------------------
__device__ __forceinline__ void insert16(float* bd, int* bi, float d, int j) {
    bd[KK - 1] = d; bi[KK - 1] = j;
#pragma unroll
    for (int t = KK - 1; t > 0; --t) {
        if (bd[t] < bd[t - 1]) {
            float td = bd[t]; bd[t] = bd[t - 1]; bd[t - 1] = td;
            int   ti = bi[t]; bi[t] = bi[t - 1]; bi[t - 1] = ti;
        }
    }
}

// prune-scan KNN: hot path uses approx dist (norm trick, f32x2); taken branch
// recomputes the EXACT reference formula for insertion (ordering identical).
__global__ __launch_bounds__(128)
void knn_part(const float* __restrict__ xyz,
              float* __restrict__ pd, int* __restrict__ pi) {
    __shared__ __align__(16) float s_x[NN], s_y[NN], s_z[NN], s_pn[NN], s_pen[NN];
    const int tid = threadIdx.x;
    const int qg  = blockIdx.x >> 2;
    const int sp  = blockIdx.x & 3;
    const int g   = qg * 128 + tid;
    const int b   = g >> 11;
    const int n   = g & (NN - 1);

    for (int j = tid; j < NN; j += 128) {
        const float* p = xyz + ((size_t)b * NN + j) * 3;
        float x = p[0], y = p[1], z = p[2];
        float pen = (x != 0.0f || y != 0.0f || z != 0.0f) ? 0.0f : LARGE_DIST;
        s_x[j] = x; s_y[j] = y; s_z[j] = z;
        s_pen[j] = pen;
        s_pn[j]  = x * x + y * y + z * z + pen;
    }
    __syncthreads();

    const float* qp = xyz + ((size_t)b * NN + n) * 3;
    const float qx = qp[0], qy = qp[1], qz = qp[2];
    const float qnorm = qx * qx + qy * qy + qz * qz;
    const unsigned long long mx2 = pack2(-2.0f * qx, -2.0f * qx);
    const unsigned long long my2 = pack2(-2.0f * qy, -2.0f * qy);
    const unsigned long long mz2 = pack2(-2.0f * qz, -2.0f * qz);

    float bd[KK]; int bi[KK];
#pragma unroll
    for (int t = 0; t < KK; t++) { bd[t] = FLT_MAX; bi[t] = 0; }
    float boundp = FLT_MAX;

    const int j0 = sp * CAND;
#pragma unroll 4
    for (int jj = 0; jj < CAND; jj += 4) {
        const int j = j0 + jj;
        ulonglong2 Xv = *(const ulonglong2*)&s_x[j];
        ulonglong2 Yv = *(const ulonglong2*)&s_y[j];
        ulonglong2 Zv = *(const ulonglong2*)&s_z[j];
        ulonglong2 Nv = *(const ulonglong2*)&s_pn[j];
        unsigned long long d0 = Nv.x, d1 = Nv.y;
        ffma2(d0, mx2, Xv.x); ffma2(d0, my2, Yv.x); ffma2(d0, mz2, Zv.x);
        ffma2(d1, mx2, Xv.y); ffma2(d1, my2, Yv.y); ffma2(d1, mz2, Zv.y);
        float2 a = unpack2(d0), c = unpack2(d1);
        float mn = fminf(fminf(a.x, a.y), fminf(c.x, c.y));
        if (mn < boundp) {
#pragma unroll
            for (int t4 = 0; t4 < 4; t4++) {
                float px = s_x[j + t4], py = s_y[j + t4], pz = s_z[j + t4];
                float dx = qx - px, dy = qy - py, dz = qz - pz;
                float d = dx * dx + dy * dy + dz * dz + s_pen[j + t4];
                if (d < bd[KK - 1]) insert16(bd, bi, d, j + t4);
            }
            boundp = bd[KK - 1] - qnorm + MARGIN;
        }
    }

    float* po = pd + ((size_t)g * SPLIT + sp) * KK;
    int*   io = pi + ((size_t)g * SPLIT + sp) * KK;
#pragma unroll
    for (int t = 0; t < KK; t++) { po[t] = bd[t]; io[t] = bi[t]; }
}

__global__ __launch_bounds__(128)
void knn_merge(const float* __restrict__ pd, const int* __restrict__ pi,
               int* __restrict__ idx_out) {
    const int g = blockIdx.x * 128 + threadIdx.x;
    float bd[KK]; int bi[KK];
#pragma unroll
    for (int t = 0; t < KK; t++) { bd[t] = FLT_MAX; bi[t] = 0; }
    const float* pp = pd + (size_t)g * SPLIT * KK;
    const int*   ii = pi + (size_t)g * SPLIT * KK;
    for (int c = 0; c < SPLIT * KK; c++) {
        float d = pp[c];
        if (d < bd[KK - 1]) insert16(bd, bi, d, ii[c]);
    }
#pragma unroll
    for (int t = 0; t < KK; t++) idx_out[(size_t)g * KK + t] = bi[t];
}

// ---------------------------------------------------------------------------
// k2: h precompute -> bf16 hi/lo
// ---------------------------------------------------------------------------
__global__ __launch_bounds__(256)
void h_kernel(const float* __restrict__ xyz, const int* __restrict__ idx,
              const float* __restrict__ w1, const float* __restrict__ b1,
              const float* __restrict__ gamma1, const float* __restrict__ beta1,
              const float* __restrict__ mean1, const float* __restrict__ var1,
              unsigned short* __restrict__ Hhi, unsigned short* __restrict__ Hlo) {
    __shared__ float sw[96], sb[32], ssc[32], ssh[32];
    const int tid = threadIdx.x;
    if (tid < 96) sw[tid] = w1[tid];
    if (tid < 32) {
        sb[tid] = b1[tid];
        float sc = gamma1[tid] * rsqrtf(var1[tid] + BN_EPS);
        ssc[tid] = sc;
        ssh[tid] = beta1[tid] - mean1[tid] * sc;
    }
    __syncthreads();

    const int g0 = blockIdx.x * 16;
    const int p  = tid >> 4;
    const int k  = tid & 15;
    const int g  = g0 + p;
    const int b  = g >> 11;
    const int n  = g & (NN - 1);
    const int nbr = idx[(size_t)g * KK + k];

    const float* qp = xyz + ((size_t)b * NN + n) * 3;
    const float* np = xyz + ((size_t)b * NN + nbr) * 3;
    float qx = qp[0], qy = qp[1], qz = qp[2];
    float px = np[0], py = np[1], pz = np[2];
    float nm = (px != 0.0f || py != 0.0f || pz != 0.0f) ? 1.0f : 0.0f;
    float r0 = nm * (px - qx), r1 = nm * (py - qy), r2 = nm * (pz - qz);

    unsigned short hh[32], ll[32];
#pragma unroll
    for (int d = 0; d < 32; d++) {
        float v = r0 * sw[d] + r1 * sw[32 + d] + r2 * sw[64 + d] + sb[d];
        v = fmaxf(v, 0.0f);
        v = v * ssc[d] + ssh[d];
        __nv_bfloat16 hv = __float2bfloat16(v);
        float res = v - __bfloat162float(hv);
        hh[d] = __bfloat16_as_ushort(hv);
        ll[d] = __bfloat16_as_ushort(__float2bfloat16(res));
    }
    size_t off = (size_t)g * 512 + k * 32;
#pragma unroll
    for (int q = 0; q < 4; q++) {
        *(uint4*)(Hhi + off + q * 8) = *(uint4*)&hh[q * 8];
        *(uint4*)(Hlo + off + q * 8) = *(uint4*)&ll[q * 8];
    }
}

// ---------------------------------------------------------------------------
// prep: transpose + bf16-split a weight matrix  W[K][N] -> out[N][K]
// ---------------------------------------------------------------------------
__global__ void prep_bT(const float* __restrict__ W,
                        unsigned short* __restrict__ hi,
                        unsigned short* __restrict__ lo, int K, int N) {
    int i = blockIdx.x * 256 + threadIdx.x;
    if (i >= K * N) return;
    int n = i % N, k = i / N;
    float v = W[i];
    __nv_bfloat16 h = __float2bfloat16(v);
    float r = v - __bfloat162float(h);
    hi[(size_t)n * K + k] = __bfloat16_as_ushort(h);
    lo[(size_t)n * K + k] = __bfloat16_as_ushort(__float2bfloat16(r));
}

// ---------------------------------------------------------------------------
// mma.sync bf16 3-term GEMM
// ---------------------------------------------------------------------------
template<int BM, int NMAT, int KTOT, int EPI>
__global__ __launch_bounds__(256)
void mma_gemm(const unsigned short* __restrict__ Ahi,
              const unsigned short* __restrict__ Alo,
              const unsigned short* __restrict__ Bhi,
              const unsigned short* __restrict__ Blo,
              const float* __restrict__ e0, const float* __restrict__ e1,
              const float* __restrict__ e2, const float* __restrict__ e3,
              const float* __restrict__ xyz, float* __restrict__ C) {
    constexpr int MT = BM / 32;
    constexpr int LDS_H = 40;
    __shared__ __align__(16) unsigned short sAh[BM * LDS_H];
    __shared__ __align__(16) unsigned short sAl[BM * LDS_H];
    __shared__ __align__(16) unsigned short sBh[128 * LDS_H];
    __shared__ __align__(16) unsigned short sBl[128 * LDS_H];

    const int tid  = threadIdx.x;
    const int lane = tid & 31;
    const int wid  = tid >> 5;
    const int wr   = wid >> 2;
    const int wc   = wid & 3;
    const int g0   = blockIdx.x * BM;
    const int col0 = blockIdx.y * 128;

    const uint32_t aHiB = smem_u32(sAh), aLoB = smem_u32(sAl);
    const uint32_t bHiB = smem_u32(sBh), bLoB = smem_u32(sBl);

    float acc[MT][4][4];
#pragma unroll
    for (int m = 0; m < MT; m++)
#pragma unroll
        for (int n = 0; n < 4; n++)
#pragma unroll
            for (int q = 0; q < 4; q++) acc[m][n][q] = 0.0f;

    const int q8 = lane >> 3;
    const int r8 = lane & 7;

    for (int k0 = 0; k0 < KTOT; k0 += 32) {
#pragma unroll
        for (int v = tid; v < BM * 4; v += 256) {
            int row = v >> 2, c8 = (v & 3) * 8;
            int dst = row * LDS_H + c8;
            size_t src = (size_t)(g0 + row) * KTOT + k0 + c8;
            *(uint4*)(sAh + dst) = *(const uint4*)(Ahi + src);
            *(uint4*)(sAl + dst) = *(const uint4*)(Alo + src);
        }
#pragma unroll
        for (int v = tid; v < 512; v += 256) {
            int row = v >> 2, c8 = (v & 3) * 8;
            int dst = row * LDS_H + c8;
            size_t src = (size_t)(col0 + row) * KTOT + k0 + c8;
            *(uint4*)(sBh + dst) = *(const uint4*)(Bhi + src);
            *(uint4*)(sBl + dst) = *(const uint4*)(Blo + src);
        }
        __syncthreads();

#pragma unroll
        for (int ks = 0; ks < 2; ks++) {
            const int kk = ks * 16;
            uint32_t ah[MT][4], al[MT][4];
#pragma unroll
            for (int m = 0; m < MT; m++) {
                int arow = wr * (BM / 2) + m * 16 + (q8 & 1) * 8 + r8;
                int acol = kk + (q8 >> 1) * 8;
                uint32_t off = (uint32_t)(arow * LDS_H + acol) * 2;
                ldm_x4(ah[m], aHiB + off);
                ldm_x4(al[m], aLoB + off);
            }
            uint32_t bh[4][2], bl[4][2];
#pragma unroll
            for (int n = 0; n < 4; n++) {
                int nrow = wc * 32 + n * 8 + r8;
                int ncol = kk + (q8 & 1) * 8;
                uint32_t off = (uint32_t)(nrow * LDS_H + ncol) * 2;
                ldm_x2(bh[n], bHiB + off);
                ldm_x2(bl[n], bLoB + off);
            }
#pragma unroll
            for (int m = 0; m < MT; m++)
#pragma unroll
                for (int n = 0; n < 4; n++) {
                    mma_bf16(acc[m][n], ah[m], bh[n]);
                    mma_bf16(acc[m][n], ah[m], bl[n]);
                    mma_bf16(acc[m][n], al[m], bh[n]);
                }
        }
        __syncthreads();
    }

#pragma unroll
    for (int m = 0; m < MT; m++) {
        int r1 = g0 + wr * (BM / 2) + m * 16 + (lane >> 2);
        int r2 = r1 + 8;
        float m1 = 1.0f, m2 = 1.0f;
        if (EPI == 1) {
            const float* p1 = xyz + (size_t)r1 * 3;
            const float* p2 = xyz + (size_t)r2 * 3;
            m1 = (p1[0] != 0.0f || p1[1] != 0.0f || p1[2] != 0.0f) ? 1.0f : 0.0f;
            m2 = (p2[0] != 0.0f || p2[1] != 0.0f || p2[2] != 0.0f) ? 1.0f : 0.0f;
        }
#pragma unroll
        for (int n = 0; n < 4; n++) {
            int c = col0 + wc * 32 + n * 8 + (lane & 3) * 2;
            float v0 = acc[m][n][0], v1 = acc[m][n][1];
            float v2 = acc[m][n][2], v3 = acc[m][n][3];
            if (EPI == 0) {
                float bb0 = e0[c], bb1 = e0[c + 1];
                v0 += bb0; v1 += bb1; v2 += bb0; v3 += bb1;
            } else {
                float sc0 = e0[c] * rsqrtf(e3[c] + BN_EPS);
                float sh0 = e1[c] - e2[c] * sc0;
                float sc1 = e0[c + 1] * rsqrtf(e3[c + 1] + BN_EPS);
                float sh1 = e1[c + 1] - e2[c + 1] * sc1;
                v0 = fmaxf(v0 * sc0 + sh0, 0.0f) * m1;
                v1 = fmaxf(v1 * sc1 + sh1, 0.0f) * m1;
                v2 = fmaxf(v2 * sc0 + sh0, 0.0f) * m2;
                v3 = fmaxf(v3 * sc1 + sh1, 0.0f) * m2;
            }
            *(float2*)(C + (size_t)r1 * NMAT + c) = make_float2(v0, v1);
            *(float2*)(C + (size_t)r2 * NMAT + c) = make_float2(v2, v3);
        }
    }
}

// ---------------------------------------------------------------------------
// FUSED k4+k5: lifted (smem only) -> transformed = X @ lifted -> bf16 hi/lo.
// 16 points / block (256 neighbor rows), 256 threads.
// ---------------------------------------------------------------------------
__global__ __launch_bounds__(256)
void lift_xform(const float* __restrict__ feat, const int* __restrict__ idx,
                const float* __restrict__ xyz, const float* __restrict__ wl,
                const float* __restrict__ gamma_l, const float* __restrict__ beta_l,
                const float* __restrict__ mean_l, const float* __restrict__ var_l,
                const float* __restrict__ Xg,
                unsigned short* __restrict__ Thi,
                unsigned short* __restrict__ Tlo) {
    extern __shared__ float sm[];
    float* As    = sm;              // [64][256] featT; later sL[16*1024]
    float* Bs    = sm + 16384;      // [64][64] wl; later sX[16*256]
    float* smask = sm + 20480;      // [256]
    float* ssc   = sm + 20736;      // [64]
    float* ssh   = sm + 20800;      // [64]

    const int tid  = threadIdx.x;
    const int g0   = blockIdx.x * 16;    // first point
    const int row0 = blockIdx.x * 256;   // first neighbor-row

    // ---- stage 1: lifted = relu(BN(gather(feat)@wl)) * nmask ----
    {
        int grow = row0 + tid;
        int nbr  = idx[grow];
        int b    = grow >> 15;
        const float* np = xyz + ((size_t)(b << 11) + nbr) * 3;
        smask[tid] = (np[0] != 0.0f || np[1] != 0.0f || np[2] != 0.0f) ? 1.0f : 0.0f;
        if (tid < 64) {
            float sc = gamma_l[tid] * rsqrtf(var_l[tid] + BN_EPS);
            ssc[tid] = sc;
            ssh[tid] = beta_l[tid] - mean_l[tid] * sc;
        }
    }
    {
        int kr = tid >> 4;
        int cc = (tid & 15) * 4;
#pragma unroll
        for (int h2 = 0; h2 < 4; h2++)
            *(float4*)&Bs[(kr + h2 * 16) * 64 + cc] =
                *(const float4*)(wl + (size_t)(kr + h2 * 16) * 64 + cc);
    }
    {
        int cc = (tid & 15) * 4;
#pragma unroll
        for (int h2 = 0; h2 < 16; h2++) {
            int r    = (tid >> 4) + h2 * 16;
            int grow = row0 + r;
            int nbr  = idx[grow];
            int b    = grow >> 15;
            float4 f = *(const float4*)(feat + ((size_t)(b << 11) + nbr) * 64 + cc);
            As[(cc + 0) * 256 + r] = f.x;
            As[(cc + 1) * 256 + r] = f.y;
            As[(cc + 2) * 256 + r] = f.z;
            As[(cc + 3) * 256 + r] = f.w;
        }
    }
    __syncthreads();

    const int tx = tid & 7;
    const int ty = tid >> 3;
    unsigned long long acc1[8][4];
#pragma unroll
    for (int i = 0; i < 8; i++)
#pragma unroll
        for (int q = 0; q < 4; q++) acc1[i][q] = 0ull;

#pragma unroll 8
    for (int kk = 0; kk < 64; kk++) {
        float a[8];
        *(float4*)&a[0] = *(const float4*)&As[kk * 256 + ty * 8];
        *(float4*)&a[4] = *(const float4*)&As[kk * 256 + ty * 8 + 4];
        ulonglong2 bA = *(const ulonglong2*)&Bs[kk * 64 + tx * 8];
        ulonglong2 bB = *(const ulonglong2*)&Bs[kk * 64 + tx * 8 + 4];
#pragma unroll
        for (int i = 0; i < 8; i++) {
            unsigned long long a2 = pack2(a[i], a[i]);
            ffma2(acc1[i][0], a2, bA.x);
            ffma2(acc1[i][1], a2, bA.y);
            ffma2(acc1[i][2], a2, bB.x);
            ffma2(acc1[i][3], a2, bB.y);
        }
    }
    __syncthreads();   // all As/Bs reads done -> overlay

    // write lifted into As region: sL[rloc*64 + col]  (rloc = p*16+k)
#pragma unroll
    for (int i = 0; i < 8; i++) {
        int rloc = ty * 8 + i;
        float m  = smask[rloc];
        float v[8];
#pragma unroll
        for (int q = 0; q < 8; q++) {
            float2 p = unpack2(acc1[i][q >> 1]);
            int nc = tx * 8 + q;
            float x = ((q & 1) ? p.y : p.x) * ssc[nc] + ssh[nc];
            v[q] = fmaxf(x, 0.0f) * m;
        }
        float* cp = As + rloc * 64 + tx * 8;
        *(float4*)cp       = make_float4(v[0], v[1], v[2], v[3]);
        *(float4*)(cp + 4) = make_float4(v[4], v[5], v[6], v[7]);
    }
    // load X tile into Bs region
    for (int e = tid * 4; e < 4096; e += 1024)
        *(float4*)&Bs[e] = *(const float4*)(Xg + (size_t)g0 * 256 + e);
    __syncthreads();

    // ---- stage 2: transformed[p][i][l] = sum_j X[p][i][j]*lifted[p][j][l] ----
    const int p = tid >> 4;
    const int i = tid & 15;

    float xr[16];
    {
        const float4* xp = (const float4*)&Bs[p * 256 + i * 16];
#pragma unroll
        for (int q = 0; q < 4; q++) *(float4*)&xr[q * 4] = xp[q];
    }

    unsigned long long acc[32];
#pragma unroll
    for (int q = 0; q < 32; q++) acc[q] = 0ull;

#pragma unroll
    for (int j = 0; j < 16; j++) {
        unsigned long long xv = pack2(xr[j], xr[j]);
        const ulonglong2* lp = (const ulonglong2*)&As[p * 1024 + j * 64];
#pragma unroll
        for (int q = 0; q < 16; q++) {
            ulonglong2 lv = lp[q];
            ffma2(acc[2 * q],     xv, lv.x);
            ffma2(acc[2 * q + 1], xv, lv.y);
        }
    }

    unsigned short hh[64], ll[64];
#pragma unroll
    for (int q = 0; q < 32; q++) {
        float2 a = unpack2(acc[q]);
        __nv_bfloat16 h0 = __float2bfloat16(a.x);
        __nv_bfloat16 h1 = __float2bfloat16(a.y);
        hh[2 * q]     = __bfloat16_as_ushort(h0);
        hh[2 * q + 1] = __bfloat16_as_ushort(h1);
        ll[2 * q]     = __bfloat16_as_ushort(__float2bfloat16(a.x - __bfloat162float(h0)));
        ll[2 * q + 1] = __bfloat16_as_ushort(__float2bfloat16(a.y - __bfloat162float(h1)));
    }
    size_t off = (size_t)(g0 + p) * 1024 + i * 64;
#pragma unroll
    for (int q = 0; q < 8; q++) {
        *(uint4*)(Thi + off + q * 8) = *(uint4*)&hh[q * 8];
        *(uint4*)(Tlo + off + q * 8) = *(uint4*)&ll[q * 8];
    }
}

// ---------------------------------------------------------------------------
extern "C" void kernel_launch(void* const* d_in, const int* in_sizes, int n_in,
                              void* d_out, int out_size) {
    const float* xyz     = (const float*)d_in[0];
    const float* feat    = (const float*)d_in[1];
    const float* w1      = (const float*)d_in[2];
    const float* b1      = (const float*)d_in[3];
    const float* gamma1  = (const float*)d_in[4];
    const float* beta1   = (const float*)d_in[5];
    const float* mean1   = (const float*)d_in[6];
    const float* var1    = (const float*)d_in[7];
    const float* w2      = (const float*)d_in[8];
    const float* b2      = (const float*)d_in[9];
    const float* wl      = (const float*)d_in[10];
    const float* gamma_l = (const float*)d_in[11];
    const float* beta_l  = (const float*)d_in[12];
    const float* mean_l  = (const float*)d_in[13];
    const float* var_l   = (const float*)d_in[14];
    const float* wf      = (const float*)d_in[15];
    const float* gamma_f = (const float*)d_in[16];
    const float* beta_f  = (const float*)d_in[17];
    const float* mean_f  = (const float*)d_in[18];
    const float* var_f   = (const float*)d_in[19];
    float* out = (float*)d_out;

    float *pd_ptr, *X_ptr;
    int *pi_ptr, *idx_ptr;
    unsigned short *hhi, *hlo, *thi, *tlo, *w2hi, *w2lo, *wfhi, *wflo;
    cudaGetSymbolAddress((void**)&pd_ptr, g_pd);
    cudaGetSymbolAddress((void**)&pi_ptr, g_pi);
    cudaGetSymbolAddress((void**)&idx_ptr, g_idx);
    cudaGetSymbolAddress((void**)&hhi, g_h_hi);
    cudaGetSymbolAddress((void**)&hlo, g_h_lo);
    cudaGetSymbolAddress((void**)&X_ptr, g_X);
    cudaGetSymbolAddress((void**)&thi, g_t_hi);
    cudaGetSymbolAddress((void**)&tlo, g_t_lo);
    cudaGetSymbolAddress((void**)&w2hi, g_w2t_hi);
    cudaGetSymbolAddress((void**)&w2lo, g_w2t_lo);
    cudaGetSymbolAddress((void**)&wfhi, g_wft_hi);
    cudaGetSymbolAddress((void**)&wflo, g_wft_lo);

    knn_part<<<(NPTS / 128) * SPLIT, 128>>>(xyz, pd_ptr, pi_ptr);
    prep_bT<<<(512 * 256 + 255) / 256, 256>>>(w2, w2hi, w2lo, 512, 256);
    prep_bT<<<(1024 * 128 + 255) / 256, 256>>>(wf, wfhi, wflo, 1024, 128);
    knn_merge<<<NPTS / 128, 128>>>(pd_ptr, pi_ptr, idx_ptr);

    h_kernel<<<NPTS / 16, 256>>>(xyz, idx_ptr, w1, b1, gamma1, beta1,
                                 mean1, var1, hhi, hlo);

    // k3: X = h @ w2 + b2   (mma.sync bf16)
    mma_gemm<128, 256, 512, 0><<<dim3(NPTS / 128, 2), 256>>>(
        hhi, hlo, w2hi, w2lo, b2, nullptr, nullptr, nullptr, xyz, X_ptr);

    // fused k4+k5
    cudaFuncSetAttribute(lift_xform,
                         cudaFuncAttributeMaxDynamicSharedMemorySize, 83456);
    lift_xform<<<NPTS / 16, 256, 83456>>>(
        feat, idx_ptr, xyz, wl, gamma_l, beta_l, mean_l, var_l,
        X_ptr, thi, tlo);

    // k6: out = relu(BN(tr @ wf)) * qmask   (mma.sync bf16)
    mma_gemm<64, 128, 1024, 1><<<dim3(NPTS / 64, 1), 256>>>(
        thi, tlo, wfhi, wflo, gamma_f, beta_f, mean_f, var_f, xyz, out);
}